// round 6
// baseline (speedup 1.0000x reference)
#include <cuda_runtime.h>
#include <cuda_bf16.h>

#define B_ 4
#define T_ 2048
#define C_ 1024
#define H_ 16
#define D_ 64
#define M_ (B_*T_)   // 8192

// Scratch for projected q,k,v in [B,T,C] layout (head h = cols h*64..h*64+63)
__device__ float g_q[M_*C_];
__device__ float g_k[M_*C_];
__device__ float g_v[M_*C_];

// Packed dual-FMA: d = a*b + d on two fp32 lanes (B300 FFMA2, only reachable via PTX)
__device__ __forceinline__ void fma2(float2 &d, float2 a, float2 b) {
    asm("fma.rn.f32x2 %0, %1, %2, %0;"
        : "+l"(reinterpret_cast<unsigned long long &>(d))
        : "l"(reinterpret_cast<unsigned long long &>(a)),
          "l"(reinterpret_cast<unsigned long long &>(b)));
}

// ---------------------------------------------------------------------------
// Kernel 1: y = x @ W^T + b for W in {Wq,Wk,Wv}  (blockIdx.z selects)
// Block tile 64(m) x 128(n), BK=16. 256 threads, 4m x 8n per thread (FFMA2).
// ---------------------------------------------------------------------------
__global__ void __launch_bounds__(256) qkv_kernel(
    const float* __restrict__ x,
    const float* __restrict__ Wq, const float* __restrict__ bq,
    const float* __restrict__ Wk, const float* __restrict__ bk,
    const float* __restrict__ Wv, const float* __restrict__ bv)
{
    __shared__ float As[16*68];    // [kk][m], padded
    __shared__ float Bs[16*132];   // [kk][n], padded

    const float* W; const float* bias; float* dst;
    if (blockIdx.z == 0)      { W = Wq; bias = bq; dst = g_q; }
    else if (blockIdx.z == 1) { W = Wk; bias = bk; dst = g_k; }
    else                      { W = Wv; bias = bv; dst = g_v; }

    const int tid = threadIdx.x;
    const int tx  = tid & 15;          // n-dir: 8 cols each
    const int ty  = tid >> 4;          // m-dir: 4 rows each
    const int m0  = blockIdx.y * 64;
    const int n0  = blockIdx.x * 128;

    const int lrow = tid >> 2;         // 0..63
    const int lcol = (tid & 3) * 4;    // 0,4,8,12

    float2 acc[4][4];
    #pragma unroll
    for (int i = 0; i < 4; i++)
        #pragma unroll
        for (int j = 0; j < 4; j++) acc[i][j] = make_float2(0.f, 0.f);

    for (int k0 = 0; k0 < C_; k0 += 16) {
        float4 a  = *(const float4*)&x[(m0 + lrow)*C_ + k0 + lcol];
        float4 b0 = *(const float4*)&W[(n0 + lrow)*C_ + k0 + lcol];
        float4 b1 = *(const float4*)&W[(n0 + 64 + lrow)*C_ + k0 + lcol];
        __syncthreads();   // previous tile fully consumed before overwrite
        As[(lcol+0)*68 + lrow] = a.x;
        As[(lcol+1)*68 + lrow] = a.y;
        As[(lcol+2)*68 + lrow] = a.z;
        As[(lcol+3)*68 + lrow] = a.w;
        Bs[(lcol+0)*132 + lrow] = b0.x;
        Bs[(lcol+1)*132 + lrow] = b0.y;
        Bs[(lcol+2)*132 + lrow] = b0.z;
        Bs[(lcol+3)*132 + lrow] = b0.w;
        Bs[(lcol+0)*132 + 64 + lrow] = b1.x;
        Bs[(lcol+1)*132 + 64 + lrow] = b1.y;
        Bs[(lcol+2)*132 + 64 + lrow] = b1.z;
        Bs[(lcol+3)*132 + 64 + lrow] = b1.w;
        __syncthreads();

        #pragma unroll
        for (int kk = 0; kk < 16; kk++) {
            float4 a4 = *(const float4*)&As[kk*68 + ty*4];
            float4 p0 = *(const float4*)&Bs[kk*132 + tx*8];
            float4 p1 = *(const float4*)&Bs[kk*132 + tx*8 + 4];
            float2 ap[4] = { make_float2(a4.x,a4.x), make_float2(a4.y,a4.y),
                             make_float2(a4.z,a4.z), make_float2(a4.w,a4.w) };
            float2 bp[4] = { make_float2(p0.x,p0.y), make_float2(p0.z,p0.w),
                             make_float2(p1.x,p1.y), make_float2(p1.z,p1.w) };
            #pragma unroll
            for (int mi = 0; mi < 4; mi++)
                #pragma unroll
                for (int nj = 0; nj < 4; nj++)
                    fma2(acc[mi][nj], ap[mi], bp[nj]);
        }
    }

    #pragma unroll
    for (int mi = 0; mi < 4; mi++) {
        int m = m0 + ty*4 + mi;
        #pragma unroll
        for (int nj = 0; nj < 4; nj++) {
            int n = n0 + tx*8 + nj*2;
            float2 v = acc[mi][nj];
            v.x += bias[n];
            v.y += bias[n+1];
            *(float2*)&dst[m*C_ + n] = v;
        }
    }
}

// ---------------------------------------------------------------------------
// Kernel 2: flash attention. One block = (b,h) x 64 q-rows; stream K/V in
// 64-row tiles. 256 threads; S and O tiles are 4x4 per thread (FFMA2 pairs).
// ---------------------------------------------------------------------------
#define TILE_F (64*68)
#define SM_ATTN (4*TILE_F*4)   // 4 tiles * 4352 floats * 4B = 69632 bytes

__global__ void __launch_bounds__(256) attn_kernel(float* __restrict__ out)
{
    extern __shared__ float sm[];
    float* Qs = sm;              // [d][i]  (scaled by 1/8)
    float* Ks = sm + TILE_F;     // [d][j]
    float* Vs = sm + 2*TILE_F;   // [j][d]
    float* Ps = sm + 3*TILE_F;   // [i][j]

    const int tid = threadIdx.x;
    const int tx  = tid & 15;    // j / d dir: 4 each
    const int ty  = tid >> 4;    // i dir: 4 each
    const int bh  = blockIdx.y;
    const int b   = bh >> 4;
    const int h   = bh & 15;
    const int i0  = blockIdx.x * 64;

    const int ld = tid & 63;     // feature lane for loads
    const int lr = tid >> 6;     // 0..3

    // Load Q tile once, transposed to [d][i], fold in softmax scale
    {
        const float* qp = g_q + (b*T_ + i0)*C_ + h*D_ + ld;
        #pragma unroll
        for (int r = 0; r < 16; r++) {
            int i = r*4 + lr;
            Qs[ld*68 + i] = qp[i*C_] * 0.125f;
        }
    }

    float2 o[4][2];
    float mrow[4], lsum[4];
    #pragma unroll
    for (int mi = 0; mi < 4; mi++) {
        o[mi][0] = o[mi][1] = make_float2(0.f, 0.f);
        mrow[mi] = -1e30f;
        lsum[mi] = 0.f;
    }

    for (int j0 = 0; j0 < T_; j0 += 64) {
        const float* kp = g_k + (b*T_ + j0)*C_ + h*D_ + ld;
        const float* vp = g_v + (b*T_ + j0)*C_ + h*D_ + ld;
        __syncthreads();   // previous tile's Ks/Vs/Ps reads complete
        #pragma unroll
        for (int r = 0; r < 16; r++) {
            int j = r*4 + lr;
            Ks[ld*68 + j] = kp[j*C_];
            Vs[j*68 + ld] = vp[j*C_];
        }
        __syncthreads();

        // S = Q K^T (scaled) : 4x4 per thread as FFMA2 pairs
        float2 s[4][2];
        #pragma unroll
        for (int mi = 0; mi < 4; mi++) s[mi][0] = s[mi][1] = make_float2(0.f, 0.f);

        #pragma unroll 16
        for (int d = 0; d < 64; d++) {
            float4 a4 = *(const float4*)&Qs[d*68 + ty*4];
            float4 b4 = *(const float4*)&Ks[d*68 + tx*4];
            float2 bp0 = make_float2(b4.x, b4.y);
            float2 bp1 = make_float2(b4.z, b4.w);
            float2 a0 = make_float2(a4.x, a4.x);
            float2 a1 = make_float2(a4.y, a4.y);
            float2 a2 = make_float2(a4.z, a4.z);
            float2 a3 = make_float2(a4.w, a4.w);
            fma2(s[0][0], a0, bp0); fma2(s[0][1], a0, bp1);
            fma2(s[1][0], a1, bp0); fma2(s[1][1], a1, bp1);
            fma2(s[2][0], a2, bp0); fma2(s[2][1], a2, bp1);
            fma2(s[3][0], a3, bp0); fma2(s[3][1], a3, bp1);
        }

        // Online softmax update (row stats replicated across the 16 tx lanes)
        #pragma unroll
        for (int mi = 0; mi < 4; mi++) {
            float rm = fmaxf(fmaxf(s[mi][0].x, s[mi][0].y),
                             fmaxf(s[mi][1].x, s[mi][1].y));
            #pragma unroll
            for (int sh = 1; sh < 16; sh <<= 1)
                rm = fmaxf(rm, __shfl_xor_sync(0xffffffffu, rm, sh));
            float mn = fmaxf(mrow[mi], rm);
            float p0 = __expf(s[mi][0].x - mn);
            float p1 = __expf(s[mi][0].y - mn);
            float p2 = __expf(s[mi][1].x - mn);
            float p3 = __expf(s[mi][1].y - mn);
            float rs = (p0 + p1) + (p2 + p3);
            #pragma unroll
            for (int sh = 1; sh < 16; sh <<= 1)
                rs += __shfl_xor_sync(0xffffffffu, rs, sh);
            float al = __expf(mrow[mi] - mn);
            lsum[mi] = lsum[mi]*al + rs;
            mrow[mi] = mn;
            o[mi][0].x *= al; o[mi][0].y *= al;
            o[mi][1].x *= al; o[mi][1].y *= al;
            *(float4*)&Ps[(ty*4+mi)*68 + tx*4] = make_float4(p0, p1, p2, p3);
        }
        __syncthreads();

        // O += P V : P read is a warp-broadcast, V read is float4
        #pragma unroll 16
        for (int j = 0; j < 64; j++) {
            float4 v4 = *(const float4*)&Vs[j*68 + tx*4];
            float2 vb0 = make_float2(v4.x, v4.y);
            float2 vb1 = make_float2(v4.z, v4.w);
            #pragma unroll
            for (int mi = 0; mi < 4; mi++) {
                float pf = Ps[(ty*4+mi)*68 + j];
                float2 pp = make_float2(pf, pf);
                fma2(o[mi][0], pp, vb0);
                fma2(o[mi][1], pp, vb1);
            }
        }
    }

    #pragma unroll
    for (int mi = 0; mi < 4; mi++) {
        float inv = 1.0f / lsum[mi];
        float4 r = make_float4(o[mi][0].x*inv, o[mi][0].y*inv,
                               o[mi][1].x*inv, o[mi][1].y*inv);
        int row = i0 + ty*4 + mi;
        *(float4*)&out[(b*T_ + row)*C_ + h*D_ + tx*4] = r;
    }
}

extern "C" void kernel_launch(void* const* d_in, const int* in_sizes, int n_in,
                              void* d_out, int out_size)
{
    const float* qx = (const float*)d_in[0];
    const float* Wq = (const float*)d_in[1];
    const float* bq = (const float*)d_in[2];
    const float* Wk = (const float*)d_in[3];
    const float* bk = (const float*)d_in[4];
    const float* Wv = (const float*)d_in[5];
    const float* bv = (const float*)d_in[6];
    float* out = (float*)d_out;

    qkv_kernel<<<dim3(C_/128, M_/64, 3), 256>>>(qx, Wq, bq, Wk, bk, Wv, bv);

    static bool attr_set_done = false;  // idempotent attribute set (not a stream op)
    cudaFuncSetAttribute(attn_kernel,
                         cudaFuncAttributeMaxDynamicSharedMemorySize, SM_ATTN);
    (void)attr_set_done;

    attn_kernel<<<dim3(T_/64, B_*H_), 256, SM_ATTN>>>(out);
}